// round 11
// baseline (speedup 1.0000x reference)
#include <cuda_runtime.h>
#include <cuda_bf16.h>

#define MAXN 50000
#define MAXE 800000
#define CH   64
#define NG   64

// ---------------- scratch (device globals) ---------------------------------
__device__ __align__(16) float g_dinv[MAXN];
__device__ __align__(16) float g_selfnorm[MAXN];
__device__ __align__(16) int   g_cnt_i[MAXN];
__device__ __align__(16) int   g_rowptr[MAXN + 1];
__device__ __align__(16) int   g_cursor[MAXN];
__device__ __align__(16) int   g_blocksum[64];
__device__ __align__(16) int2  g_cedge[MAXE];      // {src, w-as-int-bits}
__device__ __align__(16) float g_hraw[MAXN * CH];
__device__ __align__(16) __nv_bfloat16 g_hbf[MAXN * CH];   // bf16 mirror for gathers
__device__ __align__(16) float g_skip[MAXN * CH];
__device__ __align__(16) float g_h   [MAXN * CH];
__device__ __align__(16) float g_pooled[NG * CH];
__device__ __align__(16) float g_cntf[NG];

// ---------------- build CSR ------------------------------------------------

__global__ void k_zero(int n) {
    int i = blockIdx.x * blockDim.x + threadIdx.x;
    if (i < n)       g_cnt_i[i] = 0;
    if (i < NG * CH) g_pooled[i] = 0.0f;
    if (i < NG)      g_cntf[i] = 0.0f;
}

// degree histogram + per-graph node counts fused
__global__ void k_hist(const int* __restrict__ dst, int nE,
                       const int* __restrict__ batch, int n) {
    int e = blockIdx.x * blockDim.x + threadIdx.x;
    if (e < nE) atomicAdd(&g_cnt_i[dst[e]], 1);
    if (e < n)  atomicAdd(&g_cntf[batch[e]], 1.0f);
}

// scan pass 1 (block reduce via shuffles) + dinv/selfnorm fused
__global__ void k_scan_p1(int n) {
    __shared__ int sh[32];
    int i = blockIdx.x * 1024 + threadIdx.x;
    int c = (i < n) ? g_cnt_i[i] : 0;
    if (i < n) {
        float r = rsqrtf((float)c + 1.0f);   // deg incl. self-loop
        g_dinv[i] = r;
        g_selfnorm[i] = r * r;
    }
    int lane = threadIdx.x & 31, wid = threadIdx.x >> 5;
    int s = c;
    #pragma unroll
    for (int o = 16; o > 0; o >>= 1) s += __shfl_down_sync(0xffffffffu, s, o);
    if (lane == 0) sh[wid] = s;
    __syncthreads();
    if (threadIdx.x < 32) {
        int v = sh[threadIdx.x];
        #pragma unroll
        for (int o = 16; o > 0; o >>= 1) v += __shfl_down_sync(0xffffffffu, v, o);
        if (threadIdx.x == 0) g_blocksum[blockIdx.x] = v;
    }
}

// pass 2: shuffle-based block scan; block offset computed in-block (warp 1)
__global__ void k_scan_p3(int n) {
    __shared__ int wsum[32];
    __shared__ int boff;
    int i = blockIdx.x * 1024 + threadIdx.x;
    int v = (i < n) ? g_cnt_i[i] : 0;
    int lane = threadIdx.x & 31, wid = threadIdx.x >> 5;

    // inclusive warp scan of own data
    int s = v;
    #pragma unroll
    for (int o = 1; o < 32; o <<= 1) {
        int u = __shfl_up_sync(0xffffffffu, s, o);
        if (lane >= o) s += u;
    }
    if (lane == 31) wsum[wid] = s;

    // warp 1: block offset = sum of prior block sums (<=64 blocks)
    if (wid == 1) {
        int s2 = 0;
        for (int t = lane; t < blockIdx.x; t += 32) s2 += g_blocksum[t];
        #pragma unroll
        for (int o = 16; o > 0; o >>= 1) s2 += __shfl_down_sync(0xffffffffu, s2, o);
        if (lane == 0) boff = s2;
    }
    __syncthreads();

    // warp 0: exclusive scan of the 32 warp sums
    if (threadIdx.x < 32) {
        int t = wsum[threadIdx.x];
        int ts = t;
        #pragma unroll
        for (int o = 1; o < 32; o <<= 1) {
            int u = __shfl_up_sync(0xffffffffu, ts, o);
            if (lane >= o) ts += u;
        }
        wsum[threadIdx.x] = ts - t;
    }
    __syncthreads();

    int ex = boff + wsum[wid] + s - v;   // exclusive prefix
    if (i < n) { g_rowptr[i] = ex; g_cursor[i] = ex; }
    if (i == n - 1) g_rowptr[n] = ex + v;
}

__global__ void k_place(const int* __restrict__ src, const int* __restrict__ dst, int nE) {
    int e = blockIdx.x * blockDim.x + threadIdx.x;
    if (e >= nE) return;
    int s = src[e], d = dst[e];
    int pos = atomicAdd(&g_cursor[d], 1);
    float w = g_dinv[s] * g_dinv[d];
    g_cedge[pos] = make_int2(s, __float_as_int(w));
}

// ---------------- bf16 pack helper -----------------------------------------
__device__ __forceinline__ uint2 pack_bf16x4(float4 v) {
    __nv_bfloat162 lo = __floats2bfloat162_rn(v.x, v.y);
    __nv_bfloat162 hi = __floats2bfloat162_rn(v.z, v.w);
    uint2 r;
    r.x = *(unsigned*)&lo;
    r.y = *(unsigned*)&hi;
    return r;
}

// ---------------- GEMM: X[n,64] @ W[64,64], 64-row tiles -------------------
// OUT = X@W (fp32) and OUTBF = bf16(X@W)
__global__ void k_gemm(const float* __restrict__ X, const float* __restrict__ W,
                       int n, float* __restrict__ OUT, __nv_bfloat16* __restrict__ OUTBF)
{
    __shared__ __align__(16) float Ws[64 * 64];
    __shared__ __align__(16) float Xs[64 * 65];

    int tid = threadIdx.x;
    int row0 = blockIdx.x * 64;

    {
        const float4* W4 = (const float4*)W;
        float4* Ws4 = (float4*)Ws;
        for (int i = tid; i < 1024; i += 256) Ws4[i] = W4[i];
    }
    for (int i = tid; i < 1024; i += 256) {
        int r  = i >> 4;
        int c4 = (i & 15) << 2;
        int gr = row0 + r;
        float4 v = make_float4(0.f, 0.f, 0.f, 0.f);
        if (gr < n) v = *(const float4*)(X + gr * 64 + c4);
        float* p = &Xs[r * 65 + c4];
        p[0] = v.x; p[1] = v.y; p[2] = v.z; p[3] = v.w;
    }
    __syncthreads();

    int tx = tid & 15;
    int ty = tid >> 4;

    float A[4][4] = {};

    #pragma unroll
    for (int k = 0; k < 64; k++) {
        float4 w = *(const float4*)&Ws[k * 64 + tx * 4];
        #pragma unroll
        for (int i = 0; i < 4; i++) {
            float xv = Xs[(ty * 4 + i) * 65 + k];
            A[i][0] = fmaf(xv, w.x, A[i][0]);
            A[i][1] = fmaf(xv, w.y, A[i][1]);
            A[i][2] = fmaf(xv, w.z, A[i][2]);
            A[i][3] = fmaf(xv, w.w, A[i][3]);
        }
    }

    int c0 = tx * 4;
    #pragma unroll
    for (int i = 0; i < 4; i++) {
        int r = row0 + ty * 4 + i;
        if (r >= n) break;
        float4 v = make_float4(A[i][0], A[i][1], A[i][2], A[i][3]);
        *(float4*)(OUT + r * 64 + c0) = v;
        *(uint2*)(OUTBF + r * 64 + c0) = pack_bf16x4(v);
    }
}

// ---------------- dual GEMM: OUTa = X@Wa (fp32 + bf16), OUTb = relu(X@Wb+bb)
__global__ void k_gemm2(const float* __restrict__ X,
                        const float* __restrict__ Wa,
                        const float* __restrict__ Wb, const float* __restrict__ bb,
                        int n, float* __restrict__ OUTa, __nv_bfloat16* __restrict__ OUTaBF,
                        float* __restrict__ OUTb)
{
    __shared__ __align__(16) float Wsa[64 * 64];
    __shared__ __align__(16) float Wsb[64 * 64];
    __shared__ __align__(16) float Xs[64 * 65];

    int tid = threadIdx.x;
    int row0 = blockIdx.x * 64;

    {
        const float4* Wa4 = (const float4*)Wa;
        const float4* Wb4 = (const float4*)Wb;
        float4* a4 = (float4*)Wsa;
        float4* b4 = (float4*)Wsb;
        for (int i = tid; i < 1024; i += 256) { a4[i] = Wa4[i]; b4[i] = Wb4[i]; }
    }
    for (int i = tid; i < 1024; i += 256) {
        int r  = i >> 4;
        int c4 = (i & 15) << 2;
        int gr = row0 + r;
        float4 v = make_float4(0.f, 0.f, 0.f, 0.f);
        if (gr < n) v = *(const float4*)(X + gr * 64 + c4);
        float* p = &Xs[r * 65 + c4];
        p[0] = v.x; p[1] = v.y; p[2] = v.z; p[3] = v.w;
    }
    __syncthreads();

    int tx = tid & 15;
    int ty = tid >> 4;

    float A[4][4] = {}, B[4][4] = {};

    #pragma unroll
    for (int k = 0; k < 64; k++) {
        float4 wa = *(const float4*)&Wsa[k * 64 + tx * 4];
        float4 wb = *(const float4*)&Wsb[k * 64 + tx * 4];
        float xr[4];
        #pragma unroll
        for (int i = 0; i < 4; i++) xr[i] = Xs[(ty * 4 + i) * 65 + k];
        #pragma unroll
        for (int i = 0; i < 4; i++) {
            A[i][0] = fmaf(xr[i], wa.x, A[i][0]);
            A[i][1] = fmaf(xr[i], wa.y, A[i][1]);
            A[i][2] = fmaf(xr[i], wa.z, A[i][2]);
            A[i][3] = fmaf(xr[i], wa.w, A[i][3]);
            B[i][0] = fmaf(xr[i], wb.x, B[i][0]);
            B[i][1] = fmaf(xr[i], wb.y, B[i][1]);
            B[i][2] = fmaf(xr[i], wb.z, B[i][2]);
            B[i][3] = fmaf(xr[i], wb.w, B[i][3]);
        }
    }

    int c0 = tx * 4;
    float4 bv = *(const float4*)(bb + c0);
    #pragma unroll
    for (int i = 0; i < 4; i++) {
        int r = row0 + ty * 4 + i;
        if (r >= n) break;
        float4 va = make_float4(A[i][0], A[i][1], A[i][2], A[i][3]);
        *(float4*)(OUTa + r * 64 + c0) = va;
        *(uint2*)(OUTaBF + r * 64 + c0) = pack_bf16x4(va);
        *(float4*)(OUTb + r * 64 + c0) =
            make_float4(fmaxf(B[i][0] + bv.x, 0.f), fmaxf(B[i][1] + bv.y, 0.f),
                        fmaxf(B[i][2] + bv.z, 0.f), fmaxf(B[i][3] + bv.w, 0.f));
    }
}

// ---------------- fused GCN aggregate (bf16 gathers, unroll-2) -------------
// OUT[d] = relu( sum_e w_e*Hbf[src_e] + selfnorm[d]*H[d] + b ) + SKIP[d]
// if DO_POOL: red-add OUT row into g_pooled[batch[d]]. 16 threads/node.
template<int DO_POOL>
__global__ void k_agg(const float* __restrict__ H, const __nv_bfloat16* __restrict__ Hbf,
                      const float* __restrict__ SKIP,
                      float* __restrict__ OUT, const float* __restrict__ b,
                      const int* __restrict__ batch, int n)
{
    int t = blockIdx.x * blockDim.x + threadIdx.x;
    int node = t >> 4;
    if (node >= n) return;
    int c4 = (t & 15) << 2;

    int beg = g_rowptr[node];
    int end = g_rowptr[node + 1];

    float sn = g_selfnorm[node];
    float4 hd = *(const float4*)(H + node * 64 + c4);
    float4 acc0 = make_float4(sn * hd.x, sn * hd.y, sn * hd.z, sn * hd.w);
    float4 acc1 = make_float4(0.f, 0.f, 0.f, 0.f);

    int j = beg;
    for (; j + 1 < end; j += 2) {
        int2 e0 = __ldg(&g_cedge[j]);
        int2 e1 = __ldg(&g_cedge[j + 1]);
        uint2 r0 = *(const uint2*)(Hbf + e0.x * 64 + c4);
        uint2 r1 = *(const uint2*)(Hbf + e1.x * 64 + c4);
        float w0 = __int_as_float(e0.y);
        float w1 = __int_as_float(e1.y);
        float2 f00 = __bfloat1622float2(*(__nv_bfloat162*)&r0.x);
        float2 f01 = __bfloat1622float2(*(__nv_bfloat162*)&r0.y);
        float2 f10 = __bfloat1622float2(*(__nv_bfloat162*)&r1.x);
        float2 f11 = __bfloat1622float2(*(__nv_bfloat162*)&r1.y);
        acc0.x = fmaf(w0, f00.x, acc0.x); acc1.x = fmaf(w1, f10.x, acc1.x);
        acc0.y = fmaf(w0, f00.y, acc0.y); acc1.y = fmaf(w1, f10.y, acc1.y);
        acc0.z = fmaf(w0, f01.x, acc0.z); acc1.z = fmaf(w1, f11.x, acc1.z);
        acc0.w = fmaf(w0, f01.y, acc0.w); acc1.w = fmaf(w1, f11.y, acc1.w);
    }
    if (j < end) {
        int2 e = __ldg(&g_cedge[j]);
        float w = __int_as_float(e.y);
        uint2 raw = *(const uint2*)(Hbf + e.x * 64 + c4);
        float2 f0 = __bfloat1622float2(*(__nv_bfloat162*)&raw.x);
        float2 f1 = __bfloat1622float2(*(__nv_bfloat162*)&raw.y);
        acc0.x = fmaf(w, f0.x, acc0.x);
        acc0.y = fmaf(w, f0.y, acc0.y);
        acc0.z = fmaf(w, f1.x, acc0.z);
        acc0.w = fmaf(w, f1.y, acc0.w);
    }
    acc0.x += acc1.x; acc0.y += acc1.y; acc0.z += acc1.z; acc0.w += acc1.w;

    float4 bv = *(const float4*)(b + c4);
    float4 sk = *(const float4*)(SKIP + node * 64 + c4);
    float4 o = make_float4(fmaxf(acc0.x + bv.x, 0.f) + sk.x,
                           fmaxf(acc0.y + bv.y, 0.f) + sk.y,
                           fmaxf(acc0.z + bv.z, 0.f) + sk.z,
                           fmaxf(acc0.w + bv.w, 0.f) + sk.w);
    *(float4*)(OUT + node * 64 + c4) = o;

    if (DO_POOL) {
        int g = batch[node];
        float* p = g_pooled + g * 64 + c4;
        asm volatile("red.global.add.v4.f32 [%0], {%1,%2,%3,%4};"
                     :: "l"(p), "f"(o.x), "f"(o.y), "f"(o.z), "f"(o.w)
                     : "memory");
    }
}

__global__ void k_final(const float* __restrict__ Wf, const float* __restrict__ bf,
                        float* __restrict__ out)
{
    int g = threadIdx.x;
    if (g >= NG) return;
    float cnt = fmaxf(g_cntf[g], 1.0f);
    float acc = 0.f;
    #pragma unroll
    for (int c = 0; c < CH; c++) acc += g_pooled[g * CH + c] * Wf[c];
    out[g] = acc / cnt + bf[0];
}

// ---------------- host -----------------------------------------------------

extern "C" void kernel_launch(void* const* d_in, const int* in_sizes, int n_in,
                              void* d_out, int out_size)
{
    const float* x   = (const float*)d_in[0];
    const float* xsc = (const float*)d_in[1];
    const float* W1  = (const float*)d_in[2];
    const float* b1  = (const float*)d_in[3];
    const float* W2  = (const float*)d_in[4];
    const float* b2  = (const float*)d_in[5];
    const float* We  = (const float*)d_in[6];
    const float* be  = (const float*)d_in[7];
    const float* W1s = (const float*)d_in[8];
    const float* b1s = (const float*)d_in[9];
    const float* W2s = (const float*)d_in[10];
    const float* b2s = (const float*)d_in[11];
    const float* Wes = (const float*)d_in[12];
    const float* bes = (const float*)d_in[13];
    const float* Wf  = (const float*)d_in[14];
    const float* bf  = (const float*)d_in[15];
    const int*   ei  = (const int*)d_in[16];
    const int*   bat = (const int*)d_in[17];

    int n  = in_sizes[0] / CH;
    int nE = in_sizes[16] / 2;
    const int* src = ei;
    const int* dst = ei + nE;
    float* out = (float*)d_out;

    float *hraw, *skip, *h;
    __nv_bfloat16* hbf;
    cudaGetSymbolAddress((void**)&hraw, g_hraw);
    cudaGetSymbolAddress((void**)&hbf,  g_hbf);
    cudaGetSymbolAddress((void**)&skip, g_skip);
    cudaGetSymbolAddress((void**)&h,    g_h);

    const int T = 256;
    int gN     = (n + T - 1) / T;
    int gE     = (nE + T - 1) / T;
    int gTile  = (n + 63) / 64;
    int gN16   = (n * 16 + T - 1) / T;
    int nB     = (n + 1023) / 1024;

    // CSR build
    k_zero<<<gN, T>>>(n);
    k_hist<<<gE, T>>>(dst, nE, bat, n);
    k_scan_p1<<<nB, 1024>>>(n);
    k_scan_p3<<<nB, 1024>>>(n);
    k_place<<<gE, T>>>(src, dst, nE);

    // ---- branch 1 ----
    k_gemm2<<<gTile, T>>>(x, W1, We, be, n, hraw, hbf, skip);
    k_agg<0><<<gN16, T>>>(hraw, hbf, skip, h, b1, bat, n);
    k_gemm<<<gTile, T>>>(h, W2, n, hraw, hbf);
    k_agg<1><<<gN16, T>>>(hraw, hbf, h, h, b2, bat, n);

    // ---- branch 2 ----
    k_gemm2<<<gTile, T>>>(xsc, W1s, Wes, bes, n, hraw, hbf, skip);
    k_agg<0><<<gN16, T>>>(hraw, hbf, skip, h, b1s, bat, n);
    k_gemm<<<gTile, T>>>(h, W2s, n, hraw, hbf);
    k_agg<1><<<gN16, T>>>(hraw, hbf, h, h, b2s, bat, n);

    k_final<<<1, 64>>>(Wf, bf, out);
}

// round 12
// speedup vs baseline: 1.1672x; 1.1672x over previous
#include <cuda_runtime.h>
#include <cuda_bf16.h>

#define MAXN 50000
#define MAXE 800000
#define CH   64
#define NG   64

// ---------------- scratch (device globals) ---------------------------------
__device__ __align__(16) float g_dinv[MAXN];
__device__ __align__(16) float g_selfnorm[MAXN];
__device__ __align__(16) int   g_cnt_i[MAXN];
__device__ __align__(16) int   g_rowptr[MAXN + 1];
__device__ __align__(16) int   g_cursor[MAXN];
__device__ __align__(16) int   g_blocksum[64];
__device__ __align__(16) int2  g_cedge[MAXE];              // {src, w-as-int-bits}
__device__ __align__(16) float g_hraw[2 * MAXN * CH];      // fp32 X@W, branch-batched
__device__ __align__(16) __nv_bfloat16 g_hcomb[MAXN * 2 * CH]; // interleaved bf16 mirror
__device__ __align__(16) float g_skip[2 * MAXN * CH];
__device__ __align__(16) float g_h   [2 * MAXN * CH];
__device__ __align__(16) float g_pooled[NG * CH];
__device__ __align__(16) float g_cntf[NG];

// ---------------- build CSR ------------------------------------------------

__global__ void k_zero(int n) {
    int i = blockIdx.x * blockDim.x + threadIdx.x;
    if (i < n)       g_cnt_i[i] = 0;
    if (i < NG * CH) g_pooled[i] = 0.0f;
    if (i < NG)      g_cntf[i] = 0.0f;
}

// degree histogram + per-graph node counts fused
__global__ void k_hist(const int* __restrict__ dst, int nE,
                       const int* __restrict__ batch, int n) {
    int e = blockIdx.x * blockDim.x + threadIdx.x;
    if (e < nE) atomicAdd(&g_cnt_i[dst[e]], 1);
    if (e < n)  atomicAdd(&g_cntf[batch[e]], 1.0f);
}

// scan pass 1 (block reduce via shuffles) + dinv/selfnorm fused
__global__ void k_scan_p1(int n) {
    __shared__ int sh[32];
    int i = blockIdx.x * 1024 + threadIdx.x;
    int c = (i < n) ? g_cnt_i[i] : 0;
    if (i < n) {
        float r = rsqrtf((float)c + 1.0f);   // deg incl. self-loop
        g_dinv[i] = r;
        g_selfnorm[i] = r * r;
    }
    int lane = threadIdx.x & 31, wid = threadIdx.x >> 5;
    int s = c;
    #pragma unroll
    for (int o = 16; o > 0; o >>= 1) s += __shfl_down_sync(0xffffffffu, s, o);
    if (lane == 0) sh[wid] = s;
    __syncthreads();
    if (threadIdx.x < 32) {
        int v = sh[threadIdx.x];
        #pragma unroll
        for (int o = 16; o > 0; o >>= 1) v += __shfl_down_sync(0xffffffffu, v, o);
        if (threadIdx.x == 0) g_blocksum[blockIdx.x] = v;
    }
}

// pass 2: shuffle-based block scan; block offset computed in-block (warp 1)
__global__ void k_scan_p3(int n) {
    __shared__ int wsum[32];
    __shared__ int boff;
    int i = blockIdx.x * 1024 + threadIdx.x;
    int v = (i < n) ? g_cnt_i[i] : 0;
    int lane = threadIdx.x & 31, wid = threadIdx.x >> 5;

    int s = v;
    #pragma unroll
    for (int o = 1; o < 32; o <<= 1) {
        int u = __shfl_up_sync(0xffffffffu, s, o);
        if (lane >= o) s += u;
    }
    if (lane == 31) wsum[wid] = s;

    if (wid == 1) {
        int s2 = 0;
        for (int t = lane; t < blockIdx.x; t += 32) s2 += g_blocksum[t];
        #pragma unroll
        for (int o = 16; o > 0; o >>= 1) s2 += __shfl_down_sync(0xffffffffu, s2, o);
        if (lane == 0) boff = s2;
    }
    __syncthreads();

    if (threadIdx.x < 32) {
        int t = wsum[threadIdx.x];
        int ts = t;
        #pragma unroll
        for (int o = 1; o < 32; o <<= 1) {
            int u = __shfl_up_sync(0xffffffffu, ts, o);
            if (lane >= o) ts += u;
        }
        wsum[threadIdx.x] = ts - t;
    }
    __syncthreads();

    int ex = boff + wsum[wid] + s - v;   // exclusive prefix
    if (i < n) { g_rowptr[i] = ex; g_cursor[i] = ex; }
    if (i == n - 1) g_rowptr[n] = ex + v;
}

__global__ void k_place(const int* __restrict__ src, const int* __restrict__ dst, int nE) {
    int e = blockIdx.x * blockDim.x + threadIdx.x;
    if (e >= nE) return;
    int s = src[e], d = dst[e];
    int pos = atomicAdd(&g_cursor[d], 1);
    float w = g_dinv[s] * g_dinv[d];
    g_cedge[pos] = make_int2(s, __float_as_int(w));
}

// ---------------- bf16 pack helper -----------------------------------------
__device__ __forceinline__ uint2 pack_bf16x4(float4 v) {
    __nv_bfloat162 lo = __floats2bfloat162_rn(v.x, v.y);
    __nv_bfloat162 hi = __floats2bfloat162_rn(v.z, v.w);
    uint2 r;
    r.x = *(unsigned*)&lo;
    r.y = *(unsigned*)&hi;
    return r;
}

// ---------------- batched GEMM (both branches): X[n,64] @ W[64,64] ---------
// blocks [0, gTile): branch 0 (X1, W_1); blocks [gTile, 2*gTile): branch 1.
// OUT fp32 at node + branch*n; HCOMB bf16 interleaved per node row.
__global__ void k_gemm_b(const float* __restrict__ X1, const float* __restrict__ X2,
                         const float* __restrict__ W1_, const float* __restrict__ W2_,
                         int n, int gTile,
                         float* __restrict__ OUT, __nv_bfloat16* __restrict__ HCOMB)
{
    __shared__ __align__(16) float Ws[64 * 64];
    __shared__ __align__(16) float Xs[64 * 65];

    int tid = threadIdx.x;
    int branch = (blockIdx.x >= gTile) ? 1 : 0;
    int row0 = (blockIdx.x - branch * gTile) * 64;
    const float* X = branch ? X2 : X1;
    const float* W = branch ? W2_ : W1_;

    {
        const float4* W4 = (const float4*)W;
        float4* Ws4 = (float4*)Ws;
        for (int i = tid; i < 1024; i += 256) Ws4[i] = W4[i];
    }
    for (int i = tid; i < 1024; i += 256) {
        int r  = i >> 4;
        int c4 = (i & 15) << 2;
        int gr = row0 + r;
        float4 v = make_float4(0.f, 0.f, 0.f, 0.f);
        if (gr < n) v = *(const float4*)(X + gr * 64 + c4);
        float* p = &Xs[r * 65 + c4];
        p[0] = v.x; p[1] = v.y; p[2] = v.z; p[3] = v.w;
    }
    __syncthreads();

    int tx = tid & 15;
    int ty = tid >> 4;

    float A[4][4] = {};

    #pragma unroll
    for (int k = 0; k < 64; k++) {
        float4 w = *(const float4*)&Ws[k * 64 + tx * 4];
        #pragma unroll
        for (int i = 0; i < 4; i++) {
            float xv = Xs[(ty * 4 + i) * 65 + k];
            A[i][0] = fmaf(xv, w.x, A[i][0]);
            A[i][1] = fmaf(xv, w.y, A[i][1]);
            A[i][2] = fmaf(xv, w.z, A[i][2]);
            A[i][3] = fmaf(xv, w.w, A[i][3]);
        }
    }

    int c0 = tx * 4;
    #pragma unroll
    for (int i = 0; i < 4; i++) {
        int r = row0 + ty * 4 + i;
        if (r >= n) break;
        float4 v = make_float4(A[i][0], A[i][1], A[i][2], A[i][3]);
        *(float4*)(OUT + (r + branch * n) * 64 + c0) = v;
        // interleaved: row = 128 bf16; group tx: [br0 4ch][br1 4ch]
        *(uint2*)(HCOMB + r * 128 + tx * 8 + branch * 4) = pack_bf16x4(v);
    }
}

// ---------------- batched dual GEMM (layer 1): raw + skip ------------------
__global__ void k_gemm2_b(const float* __restrict__ X1, const float* __restrict__ X2,
                          const float* __restrict__ Wa1, const float* __restrict__ Wa2,
                          const float* __restrict__ Wb1, const float* __restrict__ Wb2,
                          const float* __restrict__ bb1, const float* __restrict__ bb2,
                          int n, int gTile,
                          float* __restrict__ OUTa, __nv_bfloat16* __restrict__ HCOMB,
                          float* __restrict__ OUTb)
{
    __shared__ __align__(16) float Wsa[64 * 64];
    __shared__ __align__(16) float Wsb[64 * 64];
    __shared__ __align__(16) float Xs[64 * 65];

    int tid = threadIdx.x;
    int branch = (blockIdx.x >= gTile) ? 1 : 0;
    int row0 = (blockIdx.x - branch * gTile) * 64;
    const float* X  = branch ? X2  : X1;
    const float* Wa = branch ? Wa2 : Wa1;
    const float* Wb = branch ? Wb2 : Wb1;
    const float* bb = branch ? bb2 : bb1;

    {
        const float4* Wa4 = (const float4*)Wa;
        const float4* Wb4 = (const float4*)Wb;
        float4* a4 = (float4*)Wsa;
        float4* b4 = (float4*)Wsb;
        for (int i = tid; i < 1024; i += 256) { a4[i] = Wa4[i]; b4[i] = Wb4[i]; }
    }
    for (int i = tid; i < 1024; i += 256) {
        int r  = i >> 4;
        int c4 = (i & 15) << 2;
        int gr = row0 + r;
        float4 v = make_float4(0.f, 0.f, 0.f, 0.f);
        if (gr < n) v = *(const float4*)(X + gr * 64 + c4);
        float* p = &Xs[r * 65 + c4];
        p[0] = v.x; p[1] = v.y; p[2] = v.z; p[3] = v.w;
    }
    __syncthreads();

    int tx = tid & 15;
    int ty = tid >> 4;

    float A[4][4] = {}, B[4][4] = {};

    #pragma unroll
    for (int k = 0; k < 64; k++) {
        float4 wa = *(const float4*)&Wsa[k * 64 + tx * 4];
        float4 wb = *(const float4*)&Wsb[k * 64 + tx * 4];
        float xr[4];
        #pragma unroll
        for (int i = 0; i < 4; i++) xr[i] = Xs[(ty * 4 + i) * 65 + k];
        #pragma unroll
        for (int i = 0; i < 4; i++) {
            A[i][0] = fmaf(xr[i], wa.x, A[i][0]);
            A[i][1] = fmaf(xr[i], wa.y, A[i][1]);
            A[i][2] = fmaf(xr[i], wa.z, A[i][2]);
            A[i][3] = fmaf(xr[i], wa.w, A[i][3]);
            B[i][0] = fmaf(xr[i], wb.x, B[i][0]);
            B[i][1] = fmaf(xr[i], wb.y, B[i][1]);
            B[i][2] = fmaf(xr[i], wb.z, B[i][2]);
            B[i][3] = fmaf(xr[i], wb.w, B[i][3]);
        }
    }

    int c0 = tx * 4;
    float4 bv = *(const float4*)(bb + c0);
    #pragma unroll
    for (int i = 0; i < 4; i++) {
        int r = row0 + ty * 4 + i;
        if (r >= n) break;
        float4 va = make_float4(A[i][0], A[i][1], A[i][2], A[i][3]);
        *(float4*)(OUTa + (r + branch * n) * 64 + c0) = va;
        *(uint2*)(HCOMB + r * 128 + tx * 8 + branch * 4) = pack_bf16x4(va);
        *(float4*)(OUTb + (r + branch * n) * 64 + c0) =
            make_float4(fmaxf(B[i][0] + bv.x, 0.f), fmaxf(B[i][1] + bv.y, 0.f),
                        fmaxf(B[i][2] + bv.z, 0.f), fmaxf(B[i][3] + bv.w, 0.f));
    }
}

// ---------------- fused dual-branch GCN aggregate --------------------------
// For both branches at once (16B interleaved gathers):
//   o_b[d] = relu( sum_e w_e*Hcomb_b[src_e] + selfnorm[d]*H_b[d] + bias_b ) + SKIP_b[d]
// if DO_POOL: red-add (o_0 + o_1) into g_pooled[batch[d]]. 16 threads/node.
template<int DO_POOL>
__global__ void k_agg2(const float* __restrict__ H, const __nv_bfloat16* __restrict__ Hcomb,
                       const float* __restrict__ SKIP,
                       float* __restrict__ OUT,
                       const float* __restrict__ b1_, const float* __restrict__ b2_,
                       const int* __restrict__ batch, int n)
{
    int t = blockIdx.x * blockDim.x + threadIdx.x;
    int node = t >> 4;
    if (node >= n) return;
    int g = t & 15;
    int c4 = g << 2;

    int beg = g_rowptr[node];
    int end = g_rowptr[node + 1];

    float sn = g_selfnorm[node];
    float4 h1 = *(const float4*)(H + node * 64 + c4);
    float4 h2 = *(const float4*)(H + (node + n) * 64 + c4);
    float4 acc1 = make_float4(sn * h1.x, sn * h1.y, sn * h1.z, sn * h1.w);
    float4 acc2 = make_float4(sn * h2.x, sn * h2.y, sn * h2.z, sn * h2.w);

    const uint4* Hc = (const uint4*)Hcomb;   // 16 uint4 per node row
    for (int j = beg; j < end; j++) {
        int2 e = __ldg(&g_cedge[j]);              // broadcast within group
        float w = __int_as_float(e.y);
        uint4 raw = __ldg(&Hc[e.x * 16 + g]);     // 16B: br1 4ch + br2 4ch
        float2 a0 = __bfloat1622float2(*(__nv_bfloat162*)&raw.x);
        float2 a1 = __bfloat1622float2(*(__nv_bfloat162*)&raw.y);
        float2 b0 = __bfloat1622float2(*(__nv_bfloat162*)&raw.z);
        float2 b1 = __bfloat1622float2(*(__nv_bfloat162*)&raw.w);
        acc1.x = fmaf(w, a0.x, acc1.x);
        acc1.y = fmaf(w, a0.y, acc1.y);
        acc1.z = fmaf(w, a1.x, acc1.z);
        acc1.w = fmaf(w, a1.y, acc1.w);
        acc2.x = fmaf(w, b0.x, acc2.x);
        acc2.y = fmaf(w, b0.y, acc2.y);
        acc2.z = fmaf(w, b1.x, acc2.z);
        acc2.w = fmaf(w, b1.y, acc2.w);
    }

    float4 bv1 = *(const float4*)(b1_ + c4);
    float4 bv2 = *(const float4*)(b2_ + c4);
    float4 sk1 = *(const float4*)(SKIP + node * 64 + c4);
    float4 sk2 = *(const float4*)(SKIP + (node + n) * 64 + c4);
    float4 o1 = make_float4(fmaxf(acc1.x + bv1.x, 0.f) + sk1.x,
                            fmaxf(acc1.y + bv1.y, 0.f) + sk1.y,
                            fmaxf(acc1.z + bv1.z, 0.f) + sk1.z,
                            fmaxf(acc1.w + bv1.w, 0.f) + sk1.w);
    float4 o2 = make_float4(fmaxf(acc2.x + bv2.x, 0.f) + sk2.x,
                            fmaxf(acc2.y + bv2.y, 0.f) + sk2.y,
                            fmaxf(acc2.z + bv2.z, 0.f) + sk2.z,
                            fmaxf(acc2.w + bv2.w, 0.f) + sk2.w);
    *(float4*)(OUT + node * 64 + c4) = o1;
    *(float4*)(OUT + (node + n) * 64 + c4) = o2;

    if (DO_POOL) {
        int gi = batch[node];
        float* p = g_pooled + gi * 64 + c4;
        asm volatile("red.global.add.v4.f32 [%0], {%1,%2,%3,%4};"
                     :: "l"(p), "f"(o1.x + o2.x), "f"(o1.y + o2.y),
                        "f"(o1.z + o2.z), "f"(o1.w + o2.w)
                     : "memory");
    }
}

__global__ void k_final(const float* __restrict__ Wf, const float* __restrict__ bf,
                        float* __restrict__ out)
{
    int g = threadIdx.x;
    if (g >= NG) return;
    float cnt = fmaxf(g_cntf[g], 1.0f);
    float acc = 0.f;
    #pragma unroll
    for (int c = 0; c < CH; c++) acc += g_pooled[g * CH + c] * Wf[c];
    out[g] = acc / cnt + bf[0];
}

// ---------------- host -----------------------------------------------------

extern "C" void kernel_launch(void* const* d_in, const int* in_sizes, int n_in,
                              void* d_out, int out_size)
{
    const float* x   = (const float*)d_in[0];
    const float* xsc = (const float*)d_in[1];
    const float* W1  = (const float*)d_in[2];
    const float* b1  = (const float*)d_in[3];
    const float* W2  = (const float*)d_in[4];
    const float* b2  = (const float*)d_in[5];
    const float* We  = (const float*)d_in[6];
    const float* be  = (const float*)d_in[7];
    const float* W1s = (const float*)d_in[8];
    const float* b1s = (const float*)d_in[9];
    const float* W2s = (const float*)d_in[10];
    const float* b2s = (const float*)d_in[11];
    const float* Wes = (const float*)d_in[12];
    const float* bes = (const float*)d_in[13];
    const float* Wf  = (const float*)d_in[14];
    const float* bf  = (const float*)d_in[15];
    const int*   ei  = (const int*)d_in[16];
    const int*   bat = (const int*)d_in[17];

    int n  = in_sizes[0] / CH;
    int nE = in_sizes[16] / 2;
    const int* src = ei;
    const int* dst = ei + nE;
    float* out = (float*)d_out;

    float *hraw, *skip, *h;
    __nv_bfloat16* hcomb;
    cudaGetSymbolAddress((void**)&hraw,  g_hraw);
    cudaGetSymbolAddress((void**)&hcomb, g_hcomb);
    cudaGetSymbolAddress((void**)&skip,  g_skip);
    cudaGetSymbolAddress((void**)&h,     g_h);

    const int T = 256;
    int gN     = (n + T - 1) / T;
    int gE     = (nE + T - 1) / T;
    int gTile  = (n + 63) / 64;
    int gN16   = (n * 16 + T - 1) / T;
    int nB     = (n + 1023) / 1024;

    // CSR build
    k_zero<<<gN, T>>>(n);
    k_hist<<<gE, T>>>(dst, nE, bat, n);
    k_scan_p1<<<nB, 1024>>>(n);
    k_scan_p3<<<nB, 1024>>>(n);
    k_place<<<gE, T>>>(src, dst, nE);

    // ---- layer 1 (both branches batched) ----
    k_gemm2_b<<<2 * gTile, T>>>(x, xsc, W1, W1s, We, Wes, be, bes,
                                n, gTile, hraw, hcomb, skip);
    k_agg2<0><<<gN16, T>>>(hraw, hcomb, skip, h, b1, b1s, bat, n);

    // ---- layer 2 (both branches batched) ----
    k_gemm_b<<<2 * gTile, T>>>(h, h + (size_t)n * CH, W2, W2s,
                               n, gTile, hraw, hcomb);
    k_agg2<1><<<gN16, T>>>(hraw, hcomb, h, h, b2, b2s, bat, n);

    k_final<<<1, 64>>>(Wf, bf, out);
}

// round 15
// speedup vs baseline: 1.2236x; 1.0484x over previous
#include <cuda_runtime.h>
#include <cuda_bf16.h>

#define MAXN 50000
#define MAXE 800000
#define CH   64
#define NG   64

// ---------------- scratch (device globals) ---------------------------------
__device__ __align__(16) float g_dinv[MAXN];
__device__ __align__(16) float g_selfnorm[MAXN];
__device__ __align__(16) int   g_cnt_i[MAXN];
__device__ __align__(16) int   g_rowptr[MAXN + 1];
__device__ __align__(16) int   g_cursor[MAXN];
__device__ __align__(16) int   g_blocksum[64];
__device__ __align__(16) int2  g_cedge[MAXE];                  // {src, w-as-int-bits}
__device__ __align__(16) __nv_bfloat16 g_hcomb[MAXN * 2 * CH]; // interleaved bf16 (both branches)
__device__ __align__(16) float g_skip[2 * MAXN * CH];
__device__ __align__(16) float g_h   [2 * MAXN * CH];
__device__ __align__(16) float g_pooled[NG * CH];
__device__ __align__(16) float g_cntf[NG];

// ---------------- build CSR ------------------------------------------------

__global__ void k_zero(int n) {
    int i = blockIdx.x * blockDim.x + threadIdx.x;
    if (i < n)       g_cnt_i[i] = 0;
    if (i < NG * CH) g_pooled[i] = 0.0f;
    if (i < NG)      g_cntf[i] = 0.0f;
}

// degree histogram + per-graph node counts fused
__global__ void k_hist(const int* __restrict__ dst, int nE,
                       const int* __restrict__ batch, int n) {
    int e = blockIdx.x * blockDim.x + threadIdx.x;
    if (e < nE) atomicAdd(&g_cnt_i[dst[e]], 1);
    if (e < n)  atomicAdd(&g_cntf[batch[e]], 1.0f);
}

// scan pass 1 (block reduce via shuffles) + dinv/selfnorm fused
__global__ void k_scan_p1(int n) {
    __shared__ int sh[32];
    int i = blockIdx.x * 1024 + threadIdx.x;
    int c = (i < n) ? g_cnt_i[i] : 0;
    if (i < n) {
        float r = rsqrtf((float)c + 1.0f);   // deg incl. self-loop
        g_dinv[i] = r;
        g_selfnorm[i] = r * r;
    }
    int lane = threadIdx.x & 31, wid = threadIdx.x >> 5;
    int s = c;
    #pragma unroll
    for (int o = 16; o > 0; o >>= 1) s += __shfl_down_sync(0xffffffffu, s, o);
    if (lane == 0) sh[wid] = s;
    __syncthreads();
    if (threadIdx.x < 32) {
        int v = sh[threadIdx.x];
        #pragma unroll
        for (int o = 16; o > 0; o >>= 1) v += __shfl_down_sync(0xffffffffu, v, o);
        if (threadIdx.x == 0) g_blocksum[blockIdx.x] = v;
    }
}

// pass 2: shuffle-based block scan; block offset computed in-block (warp 1)
__global__ void k_scan_p3(int n) {
    __shared__ int wsum[32];
    __shared__ int boff;
    int i = blockIdx.x * 1024 + threadIdx.x;
    int v = (i < n) ? g_cnt_i[i] : 0;
    int lane = threadIdx.x & 31, wid = threadIdx.x >> 5;

    int s = v;
    #pragma unroll
    for (int o = 1; o < 32; o <<= 1) {
        int u = __shfl_up_sync(0xffffffffu, s, o);
        if (lane >= o) s += u;
    }
    if (lane == 31) wsum[wid] = s;

    if (wid == 1) {
        int s2 = 0;
        for (int t = lane; t < blockIdx.x; t += 32) s2 += g_blocksum[t];
        #pragma unroll
        for (int o = 16; o > 0; o >>= 1) s2 += __shfl_down_sync(0xffffffffu, s2, o);
        if (lane == 0) boff = s2;
    }
    __syncthreads();

    if (threadIdx.x < 32) {
        int t = wsum[threadIdx.x];
        int ts = t;
        #pragma unroll
        for (int o = 1; o < 32; o <<= 1) {
            int u = __shfl_up_sync(0xffffffffu, ts, o);
            if (lane >= o) ts += u;
        }
        wsum[threadIdx.x] = ts - t;
    }
    __syncthreads();

    int ex = boff + wsum[wid] + s - v;   // exclusive prefix
    if (i < n) { g_rowptr[i] = ex; g_cursor[i] = ex; }
    if (i == n - 1) g_rowptr[n] = ex + v;
}

__global__ void k_place(const int* __restrict__ src, const int* __restrict__ dst, int nE) {
    int e = blockIdx.x * blockDim.x + threadIdx.x;
    if (e >= nE) return;
    int s = src[e], d = dst[e];
    int pos = atomicAdd(&g_cursor[d], 1);
    float w = g_dinv[s] * g_dinv[d];
    g_cedge[pos] = make_int2(s, __float_as_int(w));
}

// ---------------- bf16 helpers ---------------------------------------------
__device__ __forceinline__ uint2 pack_bf16x4(float4 v) {
    __nv_bfloat162 lo = __floats2bfloat162_rn(v.x, v.y);
    __nv_bfloat162 hi = __floats2bfloat162_rn(v.z, v.w);
    uint2 r;
    r.x = *(unsigned*)&lo;
    r.y = *(unsigned*)&hi;
    return r;
}
// exact bf16 -> f32 widening via bit ops (no F2F)
__device__ __forceinline__ float bf_lo(unsigned u) { return __int_as_float((int)(u << 16)); }
__device__ __forceinline__ float bf_hi(unsigned u) { return __int_as_float((int)(u & 0xFFFF0000u)); }

// ---------------- batched GEMM (both branches): X[n,64] @ W[64,64] ---------
// blocks [0, gTile): branch 0; [gTile, 2*gTile): branch 1.
// Writes ONLY the interleaved bf16 mirror HCOMB.
__global__ void k_gemm_b(const float* __restrict__ X1, const float* __restrict__ X2,
                         const float* __restrict__ W1_, const float* __restrict__ W2_,
                         int n, int gTile,
                         __nv_bfloat16* __restrict__ HCOMB)
{
    __shared__ __align__(16) float Ws[64 * 64];
    __shared__ __align__(16) float Xs[64 * 65];

    int tid = threadIdx.x;
    int branch = (blockIdx.x >= gTile) ? 1 : 0;
    int row0 = (blockIdx.x - branch * gTile) * 64;
    const float* X = branch ? X2 : X1;
    const float* W = branch ? W2_ : W1_;

    {
        const float4* W4 = (const float4*)W;
        float4* Ws4 = (float4*)Ws;
        for (int i = tid; i < 1024; i += 256) Ws4[i] = W4[i];
    }
    for (int i = tid; i < 1024; i += 256) {
        int r  = i >> 4;
        int c4 = (i & 15) << 2;
        int gr = row0 + r;
        float4 v = make_float4(0.f, 0.f, 0.f, 0.f);
        if (gr < n) v = *(const float4*)(X + gr * 64 + c4);
        float* p = &Xs[r * 65 + c4];
        p[0] = v.x; p[1] = v.y; p[2] = v.z; p[3] = v.w;
    }
    __syncthreads();

    int tx = tid & 15;
    int ty = tid >> 4;

    float A[4][4] = {};

    #pragma unroll
    for (int k = 0; k < 64; k++) {
        float4 w = *(const float4*)&Ws[k * 64 + tx * 4];
        #pragma unroll
        for (int i = 0; i < 4; i++) {
            float xv = Xs[(ty * 4 + i) * 65 + k];
            A[i][0] = fmaf(xv, w.x, A[i][0]);
            A[i][1] = fmaf(xv, w.y, A[i][1]);
            A[i][2] = fmaf(xv, w.z, A[i][2]);
            A[i][3] = fmaf(xv, w.w, A[i][3]);
        }
    }

    #pragma unroll
    for (int i = 0; i < 4; i++) {
        int r = row0 + ty * 4 + i;
        if (r >= n) break;
        float4 v = make_float4(A[i][0], A[i][1], A[i][2], A[i][3]);
        // interleaved: row = 128 bf16; group tx: [br0 4ch][br1 4ch]
        *(uint2*)(HCOMB + r * 128 + tx * 8 + branch * 4) = pack_bf16x4(v);
    }
}

// ---------------- batched dual GEMM (layer 1): hcomb + fp32 skip -----------
__global__ void k_gemm2_b(const float* __restrict__ X1, const float* __restrict__ X2,
                          const float* __restrict__ Wa1, const float* __restrict__ Wa2,
                          const float* __restrict__ Wb1, const float* __restrict__ Wb2,
                          const float* __restrict__ bb1, const float* __restrict__ bb2,
                          int n, int gTile,
                          __nv_bfloat16* __restrict__ HCOMB,
                          float* __restrict__ OUTb)
{
    __shared__ __align__(16) float Wsa[64 * 64];
    __shared__ __align__(16) float Wsb[64 * 64];
    __shared__ __align__(16) float Xs[64 * 65];

    int tid = threadIdx.x;
    int branch = (blockIdx.x >= gTile) ? 1 : 0;
    int row0 = (blockIdx.x - branch * gTile) * 64;
    const float* X  = branch ? X2  : X1;
    const float* Wa = branch ? Wa2 : Wa1;
    const float* Wb = branch ? Wb2 : Wb1;
    const float* bb = branch ? bb2 : bb1;

    {
        const float4* Wa4 = (const float4*)Wa;
        const float4* Wb4 = (const float4*)Wb;
        float4* a4 = (float4*)Wsa;
        float4* b4 = (float4*)Wsb;
        for (int i = tid; i < 1024; i += 256) { a4[i] = Wa4[i]; b4[i] = Wb4[i]; }
    }
    for (int i = tid; i < 1024; i += 256) {
        int r  = i >> 4;
        int c4 = (i & 15) << 2;
        int gr = row0 + r;
        float4 v = make_float4(0.f, 0.f, 0.f, 0.f);
        if (gr < n) v = *(const float4*)(X + gr * 64 + c4);
        float* p = &Xs[r * 65 + c4];
        p[0] = v.x; p[1] = v.y; p[2] = v.z; p[3] = v.w;
    }
    __syncthreads();

    int tx = tid & 15;
    int ty = tid >> 4;

    float A[4][4] = {}, B[4][4] = {};

    #pragma unroll
    for (int k = 0; k < 64; k++) {
        float4 wa = *(const float4*)&Wsa[k * 64 + tx * 4];
        float4 wb = *(const float4*)&Wsb[k * 64 + tx * 4];
        float xr[4];
        #pragma unroll
        for (int i = 0; i < 4; i++) xr[i] = Xs[(ty * 4 + i) * 65 + k];
        #pragma unroll
        for (int i = 0; i < 4; i++) {
            A[i][0] = fmaf(xr[i], wa.x, A[i][0]);
            A[i][1] = fmaf(xr[i], wa.y, A[i][1]);
            A[i][2] = fmaf(xr[i], wa.z, A[i][2]);
            A[i][3] = fmaf(xr[i], wa.w, A[i][3]);
            B[i][0] = fmaf(xr[i], wb.x, B[i][0]);
            B[i][1] = fmaf(xr[i], wb.y, B[i][1]);
            B[i][2] = fmaf(xr[i], wb.z, B[i][2]);
            B[i][3] = fmaf(xr[i], wb.w, B[i][3]);
        }
    }

    int c0 = tx * 4;
    float4 bv = *(const float4*)(bb + c0);
    #pragma unroll
    for (int i = 0; i < 4; i++) {
        int r = row0 + ty * 4 + i;
        if (r >= n) break;
        float4 va = make_float4(A[i][0], A[i][1], A[i][2], A[i][3]);
        *(uint2*)(HCOMB + r * 128 + tx * 8 + branch * 4) = pack_bf16x4(va);
        *(float4*)(OUTb + (r + branch * n) * 64 + c0) =
            make_float4(fmaxf(B[i][0] + bv.x, 0.f), fmaxf(B[i][1] + bv.y, 0.f),
                        fmaxf(B[i][2] + bv.z, 0.f), fmaxf(B[i][3] + bv.w, 0.f));
    }
}

// ---------------- fused dual-branch GCN aggregate --------------------------
// Self term + neighbors all from the interleaved bf16 mirror; edge prefetch.
//   o_b[d] = relu( sum_e w_e*Hcomb_b[src_e] + selfnorm[d]*Hcomb_b[d] + bias_b ) + SKIP_b[d]
// if DO_POOL: red-add (o_0 + o_1) into g_pooled[batch[d]]. 16 threads/node.
template<int DO_POOL>
__global__ void k_agg2(const __nv_bfloat16* __restrict__ Hcomb,
                       const float* __restrict__ SKIP,
                       float* __restrict__ OUT,
                       const float* __restrict__ b1_, const float* __restrict__ b2_,
                       const int* __restrict__ batch, int n)
{
    int t = blockIdx.x * blockDim.x + threadIdx.x;
    int node = t >> 4;
    if (node >= n) return;
    int g = t & 15;
    int c4 = g << 2;

    int beg = g_rowptr[node];
    int end = g_rowptr[node + 1];

    const uint4* Hc = (const uint4*)Hcomb;   // 16 uint4 per node row

    // self term (bf16, weight = selfnorm)
    float sn = g_selfnorm[node];
    uint4 rs = __ldg(&Hc[node * 16 + g]);
    float4 acc1 = make_float4(sn * bf_lo(rs.x), sn * bf_hi(rs.x),
                              sn * bf_lo(rs.y), sn * bf_hi(rs.y));
    float4 acc2 = make_float4(sn * bf_lo(rs.z), sn * bf_hi(rs.z),
                              sn * bf_lo(rs.w), sn * bf_hi(rs.w));

    // edge loop with next-record prefetch (keeps edge load off critical path)
    int2 e = (beg < end) ? __ldg(&g_cedge[beg]) : make_int2(0, 0);
    for (int j = beg; j < end; j++) {
        int2 e_cur = e;
        if (j + 1 < end) e = __ldg(&g_cedge[j + 1]);
        float w = __int_as_float(e_cur.y);
        uint4 raw = __ldg(&Hc[e_cur.x * 16 + g]);   // 16B: br1 4ch + br2 4ch
        acc1.x = fmaf(w, bf_lo(raw.x), acc1.x);
        acc1.y = fmaf(w, bf_hi(raw.x), acc1.y);
        acc1.z = fmaf(w, bf_lo(raw.y), acc1.z);
        acc1.w = fmaf(w, bf_hi(raw.y), acc1.w);
        acc2.x = fmaf(w, bf_lo(raw.z), acc2.x);
        acc2.y = fmaf(w, bf_hi(raw.z), acc2.y);
        acc2.z = fmaf(w, bf_lo(raw.w), acc2.z);
        acc2.w = fmaf(w, bf_hi(raw.w), acc2.w);
    }

    float4 bv1 = *(const float4*)(b1_ + c4);
    float4 bv2 = *(const float4*)(b2_ + c4);
    float4 sk1 = *(const float4*)(SKIP + node * 64 + c4);
    float4 sk2 = *(const float4*)(SKIP + (node + n) * 64 + c4);
    float4 o1 = make_float4(fmaxf(acc1.x + bv1.x, 0.f) + sk1.x,
                            fmaxf(acc1.y + bv1.y, 0.f) + sk1.y,
                            fmaxf(acc1.z + bv1.z, 0.f) + sk1.z,
                            fmaxf(acc1.w + bv1.w, 0.f) + sk1.w);
    float4 o2 = make_float4(fmaxf(acc2.x + bv2.x, 0.f) + sk2.x,
                            fmaxf(acc2.y + bv2.y, 0.f) + sk2.y,
                            fmaxf(acc2.z + bv2.z, 0.f) + sk2.z,
                            fmaxf(acc2.w + bv2.w, 0.f) + sk2.w);
    *(float4*)(OUT + node * 64 + c4) = o1;
    *(float4*)(OUT + (node + n) * 64 + c4) = o2;

    if (DO_POOL) {
        int gi = batch[node];
        float* p = g_pooled + gi * 64 + c4;
        asm volatile("red.global.add.v4.f32 [%0], {%1,%2,%3,%4};"
                     :: "l"(p), "f"(o1.x + o2.x), "f"(o1.y + o2.y),
                        "f"(o1.z + o2.z), "f"(o1.w + o2.w)
                     : "memory");
    }
}

__global__ void k_final(const float* __restrict__ Wf, const float* __restrict__ bf,
                        float* __restrict__ out)
{
    int g = threadIdx.x;
    if (g >= NG) return;
    float cnt = fmaxf(g_cntf[g], 1.0f);
    float acc = 0.f;
    #pragma unroll
    for (int c = 0; c < CH; c++) acc += g_pooled[g * CH + c] * Wf[c];
    out[g] = acc / cnt + bf[0];
}

// ---------------- host -----------------------------------------------------

extern "C" void kernel_launch(void* const* d_in, const int* in_sizes, int n_in,
                              void* d_out, int out_size)
{
    const float* x   = (const float*)d_in[0];
    const float* xsc = (const float*)d_in[1];
    const float* W1  = (const float*)d_in[2];
    const float* b1  = (const float*)d_in[3];
    const float* W2  = (const float*)d_in[4];
    const float* b2  = (const float*)d_in[5];
    const float* We  = (const float*)d_in[6];
    const float* be  = (const float*)d_in[7];
    const float* W1s = (const float*)d_in[8];
    const float* b1s = (const float*)d_in[9];
    const float* W2s = (const float*)d_in[10];
    const float* b2s = (const float*)d_in[11];
    const float* Wes = (const float*)d_in[12];
    const float* bes = (const float*)d_in[13];
    const float* Wf  = (const float*)d_in[14];
    const float* bf  = (const float*)d_in[15];
    const int*   ei  = (const int*)d_in[16];
    const int*   bat = (const int*)d_in[17];

    int n  = in_sizes[0] / CH;
    int nE = in_sizes[16] / 2;
    const int* src = ei;
    const int* dst = ei + nE;
    float* out = (float*)d_out;

    float *skip, *h;
    __nv_bfloat16* hcomb;
    cudaGetSymbolAddress((void**)&hcomb, g_hcomb);
    cudaGetSymbolAddress((void**)&skip,  g_skip);
    cudaGetSymbolAddress((void**)&h,     g_h);

    const int T = 256;
    int gN     = (n + T - 1) / T;
    int gE     = (nE + T - 1) / T;
    int gTile  = (n + 63) / 64;
    int gN16   = (n * 16 + T - 1) / T;
    int nB     = (n + 1023) / 1024;

    // CSR build
    k_zero<<<gN, T>>>(n);
    k_hist<<<gE, T>>>(dst, nE, bat, n);
    k_scan_p1<<<nB, 1024>>>(n);
    k_scan_p3<<<nB, 1024>>>(n);
    k_place<<<gE, T>>>(src, dst, nE);

    // ---- layer 1 (both branches batched) ----
    k_gemm2_b<<<2 * gTile, T>>>(x, xsc, W1, W1s, We, Wes, be, bes,
                                n, gTile, hcomb, skip);
    k_agg2<0><<<gN16, T>>>(hcomb, skip, h, b1, b1s, bat, n);

    // ---- layer 2 (both branches batched) ----
    k_gemm_b<<<2 * gTile, T>>>(h, h + (size_t)n * CH, W2, W2s,
                               n, gTile, hcomb);
    k_agg2<1><<<gN16, T>>>(hcomb, h, h, b2, b2s, bat, n);

    k_final<<<1, 64>>>(Wf, bf, out);
}